// round 3
// baseline (speedup 1.0000x reference)
#include <cuda_runtime.h>
#include <cuda_bf16.h>

// ---------------------------------------------------------------------------
// SchNet interaction block, fp32 baseline.
//   v   = x @ lin1_w + lin1_b
//   W   = ssp(edge_attr @ cf1_w); W = ssp(W @ cf2_w + cf2_b)
//   msg = v[src] * W * edge_weight ; agg = segment_sum(msg, dst)
//   out = x + (ssp(agg @ lin2_w + lin2_b) @ lin3_w + lin3_b)
// NOTE: edge_index arrives as int32 (jax x64 disabled coerces jnp.int64).
// ---------------------------------------------------------------------------

#define H   128
#define EC  64
#define NN  100000          // number of nodes

static __device__ float g_v[(size_t)NN * H];    // pre-projected node features
static __device__ float g_agg[(size_t)NN * H];  // scatter-sum accumulator

__device__ __forceinline__ float ssp(float z) {
    // shifted softplus: softplus(z) - log(2), numerically stable
    float sp = fmaxf(z, 0.0f) + log1pf(__expf(-fabsf(z)));
    return sp - 0.69314718055994530942f;
}

// ---------------------------------------------------------------------------
// Kernel 0: zero the aggregation buffer (vectorized)
// ---------------------------------------------------------------------------
__global__ void k_zero_agg() {
    size_t i = (size_t)blockIdx.x * blockDim.x + threadIdx.x;
    float4* p = reinterpret_cast<float4*>(g_agg);
    size_t n4 = (size_t)NN * H / 4;
    if (i < n4) p[i] = make_float4(0.f, 0.f, 0.f, 0.f);
}

// ---------------------------------------------------------------------------
// Kernel 1: node pre-projection  v = x @ lin1_w + lin1_b
// 128 threads (thread j = output column j), R1 rows register-blocked,
// weights resident in shared memory, persistent grid-stride over rows.
// ---------------------------------------------------------------------------
#define R1 8
__global__ void k_node_proj(const float* __restrict__ x,
                            const float* __restrict__ w,
                            const float* __restrict__ b) {
    extern __shared__ float s[];
    float* sw = s;             // H*H
    float* sb = sw + H * H;    // H
    float* sx = sb + H;        // R1*H

    for (int i = threadIdx.x; i < H * H; i += blockDim.x) sw[i] = w[i];
    if (threadIdx.x < H) sb[threadIdx.x] = b[threadIdx.x];
    __syncthreads();

    const int j = threadIdx.x;
    for (int row0 = blockIdx.x * R1; row0 < NN; row0 += gridDim.x * R1) {
        const int nr = min(R1, NN - row0);
        __syncthreads();
        for (int r = 0; r < nr; r++) sx[r * H + j] = x[(size_t)(row0 + r) * H + j];
        __syncthreads();

        float acc[R1];
        #pragma unroll
        for (int r = 0; r < R1; r++) acc[r] = sb[j];

        #pragma unroll 4
        for (int k = 0; k < H; k++) {
            const float wv = sw[k * H + j];
            #pragma unroll
            for (int r = 0; r < R1; r++) acc[r] = fmaf(sx[r * H + k], wv, acc[r]);
        }
        for (int r = 0; r < nr; r++) g_v[(size_t)(row0 + r) * H + j] = acc[r];
    }
}

// ---------------------------------------------------------------------------
// Kernel 2: fused edge pipeline (dominant kernel)
//   per edge: W1 = ssp(ea @ cf1_w) ; W2 = ssp(W1 @ cf2_w + b)
//             msg = v[src] * W2 * ew ; atomicAdd into agg[dst]
// Persistent CTAs, cf1_w (32KB) + cf2_w (64KB) resident in smem,
// TE-edge register tiles, thread j owns output column j.
// ---------------------------------------------------------------------------
#define TE 8
__global__ void k_edges(const float* __restrict__ ea,
                        const float* __restrict__ ew,
                        const float* __restrict__ cf1,
                        const float* __restrict__ cf2,
                        const float* __restrict__ cf2b,
                        const int* __restrict__ eidx,   // int32! [2, E]
                        int E) {
    extern __shared__ float s[];
    float* s_cf1 = s;                      // EC*H   = 8192
    float* s_cf2 = s_cf1 + EC * H;         // H*H    = 16384
    float* s_b   = s_cf2 + H * H;          // H
    float* s_ea  = s_b + H;                // TE*EC
    float* s_w1  = s_ea + TE * EC;         // TE*H

    for (int i = threadIdx.x; i < EC * H; i += blockDim.x) s_cf1[i] = cf1[i];
    for (int i = threadIdx.x; i < H * H; i += blockDim.x)  s_cf2[i] = cf2[i];
    if (threadIdx.x < H) s_b[threadIdx.x] = cf2b[threadIdx.x];
    __syncthreads();

    const int j = threadIdx.x;

    for (long long t0 = (long long)blockIdx.x * TE; t0 < E;
         t0 += (long long)gridDim.x * TE) {
        const int ne = (int)min((long long)TE, (long long)E - t0);

        __syncthreads();   // protect s_ea / s_w1 reuse across iterations
        for (int i = j; i < ne * EC; i += blockDim.x)
            s_ea[i] = ea[t0 * EC + i];
        __syncthreads();

        // --- layer 1: [TE,64] @ [64,128], thread j -> column j ---
        float a1[TE];
        #pragma unroll
        for (int e = 0; e < TE; e++) a1[e] = 0.0f;

        #pragma unroll 4
        for (int k = 0; k < EC; k++) {
            const float wv = s_cf1[k * H + j];
            #pragma unroll
            for (int e = 0; e < TE; e++)
                a1[e] = fmaf(s_ea[e * EC + k], wv, a1[e]);
        }
        #pragma unroll
        for (int e = 0; e < TE; e++) s_w1[e * H + j] = ssp(a1[e]);
        __syncthreads();

        // --- layer 2: [TE,128] @ [128,128] + bias ---
        float a2[TE];
        #pragma unroll
        for (int e = 0; e < TE; e++) a2[e] = s_b[j];

        #pragma unroll 4
        for (int k = 0; k < H; k++) {
            const float wv = s_cf2[k * H + j];
            #pragma unroll
            for (int e = 0; e < TE; e++)
                a2[e] = fmaf(s_w1[e * H + k], wv, a2[e]);
        }

        // --- gather, modulate, scatter-add ---
        #pragma unroll
        for (int e = 0; e < TE; e++) {
            if (e < ne) {
                const long long eg  = t0 + e;
                const size_t src = (size_t)(unsigned)eidx[eg];
                const size_t dst = (size_t)(unsigned)eidx[(size_t)E + eg];
                const float m = ssp(a2[e]) * g_v[src * H + j] * ew[eg];
                atomicAdd(&g_agg[dst * H + j], m);
            }
        }
    }
}

// ---------------------------------------------------------------------------
// Kernel 3: post MLP + residual
//   out = x + (ssp(agg @ lin2_w + lin2_b) @ lin3_w + lin3_b)
// ---------------------------------------------------------------------------
#define R3 4
__global__ void k_post(const float* __restrict__ x,
                       const float* __restrict__ w2,
                       const float* __restrict__ b2,
                       const float* __restrict__ w3,
                       const float* __restrict__ b3,
                       float* __restrict__ out) {
    extern __shared__ float s[];
    float* s_w2 = s;                  // H*H
    float* s_w3 = s_w2 + H * H;       // H*H
    float* s_b2 = s_w3 + H * H;       // H
    float* s_b3 = s_b2 + H;           // H
    float* s_ag = s_b3 + H;           // R3*H
    float* s_h  = s_ag + R3 * H;      // R3*H

    for (int i = threadIdx.x; i < H * H; i += blockDim.x) {
        s_w2[i] = w2[i];
        s_w3[i] = w3[i];
    }
    if (threadIdx.x < H) {
        s_b2[threadIdx.x] = b2[threadIdx.x];
        s_b3[threadIdx.x] = b3[threadIdx.x];
    }
    __syncthreads();

    const int j = threadIdx.x;
    for (int row0 = blockIdx.x * R3; row0 < NN; row0 += gridDim.x * R3) {
        const int nr = min(R3, NN - row0);
        __syncthreads();
        for (int r = 0; r < nr; r++)
            s_ag[r * H + j] = g_agg[(size_t)(row0 + r) * H + j];
        __syncthreads();

        float h[R3];
        #pragma unroll
        for (int r = 0; r < R3; r++) h[r] = s_b2[j];
        #pragma unroll 4
        for (int k = 0; k < H; k++) {
            const float wv = s_w2[k * H + j];
            #pragma unroll
            for (int r = 0; r < R3; r++) h[r] = fmaf(s_ag[r * H + k], wv, h[r]);
        }
        #pragma unroll
        for (int r = 0; r < R3; r++) s_h[r * H + j] = ssp(h[r]);
        __syncthreads();

        float o[R3];
        #pragma unroll
        for (int r = 0; r < R3; r++) o[r] = s_b3[j];
        #pragma unroll 4
        for (int k = 0; k < H; k++) {
            const float wv = s_w3[k * H + j];
            #pragma unroll
            for (int r = 0; r < R3; r++) o[r] = fmaf(s_h[r * H + k], wv, o[r]);
        }
        for (int r = 0; r < nr; r++)
            out[(size_t)(row0 + r) * H + j] =
                x[(size_t)(row0 + r) * H + j] + o[r];
    }
}

// ---------------------------------------------------------------------------
// launch
// ---------------------------------------------------------------------------
extern "C" void kernel_launch(void* const* d_in, const int* in_sizes, int n_in,
                              void* d_out, int out_size) {
    const float* x      = (const float*)d_in[0];
    const float* ea     = (const float*)d_in[1];
    const float* ew     = (const float*)d_in[2];
    const float* lin1_w = (const float*)d_in[3];
    const float* lin1_b = (const float*)d_in[4];
    const float* cf1_w  = (const float*)d_in[5];
    const float* cf2_w  = (const float*)d_in[6];
    const float* cf2_b  = (const float*)d_in[7];
    const float* lin2_w = (const float*)d_in[8];
    const float* lin2_b = (const float*)d_in[9];
    const float* lin3_w = (const float*)d_in[10];
    const float* lin3_b = (const float*)d_in[11];
    const int*   ei     = (const int*)d_in[12];   // int32 [2, E]
    float* out = (float*)d_out;

    const int E = in_sizes[2];   // edge_weight has E elements

    const int smem_node = (H * H + H + R1 * H) * (int)sizeof(float);
    const int smem_edge = (EC * H + H * H + H + TE * EC + TE * H) * (int)sizeof(float);
    const int smem_post = (2 * H * H + 2 * H + 2 * R3 * H) * (int)sizeof(float);

    cudaFuncSetAttribute(k_node_proj, cudaFuncAttributeMaxDynamicSharedMemorySize, smem_node);
    cudaFuncSetAttribute(k_edges,     cudaFuncAttributeMaxDynamicSharedMemorySize, smem_edge);
    cudaFuncSetAttribute(k_post,      cudaFuncAttributeMaxDynamicSharedMemorySize, smem_post);

    // zero agg: NN*H/4 float4 stores
    {
        const size_t n4 = (size_t)NN * H / 4;
        const int thr = 256;
        const int blk = (int)((n4 + thr - 1) / thr);
        k_zero_agg<<<blk, thr>>>();
    }

    k_node_proj<<<444, 128, smem_node>>>(x, lin1_w, lin1_b);
    k_edges<<<296, 128, smem_edge>>>(ea, ew, cf1_w, cf2_w, cf2_b, ei, E);
    k_post<<<148, 128, smem_post>>>(x, lin2_w, lin2_b, lin3_w, lin3_b, out);
}

// round 4
// speedup vs baseline: 2.5807x; 2.5807x over previous
#include <cuda_runtime.h>
#include <cuda_bf16.h>

// ---------------------------------------------------------------------------
// SchNet interaction block, fp32, register-micro-tiled SIMT GEMMs.
//   v   = x @ lin1_w + lin1_b
//   W   = ssp(edge_attr @ cf1_w); W = ssp(W @ cf2_w + cf2_b)
//   msg = v[src] * W * edge_weight ; agg = segment_sum(msg, dst)
//   out = x + (ssp(agg @ lin2_w + lin2_b) @ lin3_w + lin3_b)
// edge_index arrives as int32 [2, E].
// Design: 256 threads, thread (ty=warp 0..7, tx=lane 0..31) computes an
// 8-row x 4-col micro-tile. A-operand reads are warp-uniform smem broadcasts,
// B-operand is one LDS.128. Row tiles are warp-private -> __syncwarp only.
// ---------------------------------------------------------------------------

#define H   128
#define EC  64
#define NN  100000
#define TR  64          // rows per CTA tile (8 warps x 8 rows)

static __device__ float g_v[(size_t)NN * H];    // pre-projected node features
static __device__ float g_agg[(size_t)NN * H];  // scatter-sum accumulator

__device__ __forceinline__ float ssp(float z) {
    // softplus(z) - log(2), stable:  max(z,0) + log1p(exp(-|z|)) - ln2
    float e = __expf(-fabsf(z));
    return fmaxf(z, 0.0f) + __logf(1.0f + e) - 0.69314718055994530942f;
}

// ---------------------------------------------------------------------------
__global__ void k_zero_agg() {
    size_t i = (size_t)blockIdx.x * blockDim.x + threadIdx.x;
    float4* p = reinterpret_cast<float4*>(g_agg);
    size_t n4 = (size_t)NN * H / 4;
    if (i < n4) p[i] = make_float4(0.f, 0.f, 0.f, 0.f);
}

// ---------------------------------------------------------------------------
// Kernel 1: v = x @ lin1_w + lin1_b     [NN,128] @ [128,128]
// ---------------------------------------------------------------------------
__global__ __launch_bounds__(256) void k_node_proj(const float* __restrict__ x,
                                                   const float* __restrict__ w,
                                                   const float* __restrict__ b) {
    extern __shared__ float s[];
    float* s_w = s;              // H*H
    float* s_b = s_w + H * H;    // H
    float* s_x = s_b + H;        // TR*H

    for (int i = threadIdx.x; i < H * H; i += 256) s_w[i] = w[i];
    if (threadIdx.x < H) s_b[threadIdx.x] = b[threadIdx.x];
    __syncthreads();

    const int tx = threadIdx.x & 31, ty = threadIdx.x >> 5;
    const float4* w4  = (const float4*)s_w;
    const float4* x4  = (const float4*)x;
    float4*       sx4 = (float4*)s_x;
    const float4 bias = *(const float4*)(s_b + 4 * tx);

    for (int t0 = blockIdx.x * TR; t0 < NN; t0 += gridDim.x * TR) {
        __syncwarp();
        // warp ty loads its own 8 rows (row = 32 float4, one per lane)
        #pragma unroll
        for (int i = 0; i < 8; i++) {
            int r = 8 * ty + i, row = t0 + r;
            float4 v = make_float4(0.f, 0.f, 0.f, 0.f);
            if (row < NN) v = x4[(size_t)row * 32 + tx];
            sx4[r * 32 + tx] = v;
        }
        __syncwarp();

        float acc[8][4];
        #pragma unroll
        for (int i = 0; i < 8; i++) {
            acc[i][0] = bias.x; acc[i][1] = bias.y;
            acc[i][2] = bias.z; acc[i][3] = bias.w;
        }
        #pragma unroll 2
        for (int k = 0; k < H; k++) {
            const float4 bf = w4[k * 32 + tx];
            #pragma unroll
            for (int i = 0; i < 8; i++) {
                const float a = s_x[(8 * ty + i) * H + k];
                acc[i][0] = fmaf(a, bf.x, acc[i][0]);
                acc[i][1] = fmaf(a, bf.y, acc[i][1]);
                acc[i][2] = fmaf(a, bf.z, acc[i][2]);
                acc[i][3] = fmaf(a, bf.w, acc[i][3]);
            }
        }
        #pragma unroll
        for (int i = 0; i < 8; i++) {
            int row = t0 + 8 * ty + i;
            if (row < NN) {
                float4 o = make_float4(acc[i][0], acc[i][1], acc[i][2], acc[i][3]);
                *(float4*)(g_v + (size_t)row * H + 4 * tx) = o;
            }
        }
    }
}

// ---------------------------------------------------------------------------
// Kernel 2: fused edge pipeline (dominant)
// ---------------------------------------------------------------------------
__global__ __launch_bounds__(256) void k_edges(const float* __restrict__ ea,
                                               const float* __restrict__ ew,
                                               const float* __restrict__ cf1,
                                               const float* __restrict__ cf2,
                                               const float* __restrict__ cf2b,
                                               const int* __restrict__ eidx,
                                               int E) {
    extern __shared__ float s[];
    float* s_cf1 = s;                      // EC*H
    float* s_cf2 = s_cf1 + EC * H;         // H*H
    float* s_b   = s_cf2 + H * H;          // H
    float* s_ea  = s_b + H;                // TR*EC
    float* s_w1  = s_ea + TR * EC;         // TR*H

    for (int i = threadIdx.x; i < EC * H; i += 256) s_cf1[i] = cf1[i];
    for (int i = threadIdx.x; i < H * H; i += 256)  s_cf2[i] = cf2[i];
    if (threadIdx.x < H) s_b[threadIdx.x] = cf2b[threadIdx.x];
    __syncthreads();

    const int tx = threadIdx.x & 31, ty = threadIdx.x >> 5;
    const float4* c14  = (const float4*)s_cf1;
    const float4* c24  = (const float4*)s_cf2;
    const float4* ea4  = (const float4*)ea;
    float4*       sea4 = (float4*)s_ea;
    float4*       sw14 = (float4*)s_w1;
    const float4 bias  = *(const float4*)(s_b + 4 * tx);

    for (long long t0 = (long long)blockIdx.x * TR; t0 < E;
         t0 += (long long)gridDim.x * TR) {
        __syncwarp();
        // warp ty loads its own 8 ea rows (row = 16 float4; 2 rows per pass)
        #pragma unroll
        for (int p = 0; p < 4; p++) {
            int r = 8 * ty + 2 * p + (tx >> 4);
            int c = tx & 15;
            long long eg = t0 + r;
            float4 v = make_float4(0.f, 0.f, 0.f, 0.f);
            if (eg < (long long)E) v = ea4[eg * 16 + c];
            sea4[r * 16 + c] = v;
        }
        __syncwarp();

        // --- layer 1: [64 rows, 64] @ [64, 128] ---
        float a1[8][4];
        #pragma unroll
        for (int i = 0; i < 8; i++)
            a1[i][0] = a1[i][1] = a1[i][2] = a1[i][3] = 0.f;

        #pragma unroll 2
        for (int k = 0; k < EC; k++) {
            const float4 bf = c14[k * 32 + tx];
            #pragma unroll
            for (int i = 0; i < 8; i++) {
                const float a = s_ea[(8 * ty + i) * EC + k];
                a1[i][0] = fmaf(a, bf.x, a1[i][0]);
                a1[i][1] = fmaf(a, bf.y, a1[i][1]);
                a1[i][2] = fmaf(a, bf.z, a1[i][2]);
                a1[i][3] = fmaf(a, bf.w, a1[i][3]);
            }
        }
        #pragma unroll
        for (int i = 0; i < 8; i++) {
            float4 o = make_float4(ssp(a1[i][0]), ssp(a1[i][1]),
                                   ssp(a1[i][2]), ssp(a1[i][3]));
            sw14[(8 * ty + i) * 32 + tx] = o;
        }
        __syncwarp();

        // --- layer 2: [64 rows, 128] @ [128, 128] + bias ---
        float a2[8][4];
        #pragma unroll
        for (int i = 0; i < 8; i++) {
            a2[i][0] = bias.x; a2[i][1] = bias.y;
            a2[i][2] = bias.z; a2[i][3] = bias.w;
        }
        #pragma unroll 2
        for (int k = 0; k < H; k++) {
            const float4 bf = c24[k * 32 + tx];
            #pragma unroll
            for (int i = 0; i < 8; i++) {
                const float a = s_w1[(8 * ty + i) * H + k];
                a2[i][0] = fmaf(a, bf.x, a2[i][0]);
                a2[i][1] = fmaf(a, bf.y, a2[i][1]);
                a2[i][2] = fmaf(a, bf.z, a2[i][2]);
                a2[i][3] = fmaf(a, bf.w, a2[i][3]);
            }
        }

        // --- gather, modulate, scatter-add (coalesced float4 per warp) ---
        #pragma unroll
        for (int i = 0; i < 8; i++) {
            const long long eg = t0 + 8 * ty + i;
            if (eg < (long long)E) {
                const int   src = eidx[eg];
                const int   dst = eidx[(size_t)E + eg];
                const float w   = ew[eg];
                const float4 v4 = *(const float4*)(g_v + (size_t)src * H + 4 * tx);
                float* ap = g_agg + (size_t)dst * H + 4 * tx;
                atomicAdd(ap + 0, ssp(a2[i][0]) * v4.x * w);
                atomicAdd(ap + 1, ssp(a2[i][1]) * v4.y * w);
                atomicAdd(ap + 2, ssp(a2[i][2]) * v4.z * w);
                atomicAdd(ap + 3, ssp(a2[i][3]) * v4.w * w);
            }
        }
    }
}

// ---------------------------------------------------------------------------
// Kernel 3: out = x + (ssp(agg @ lin2_w + lin2_b) @ lin3_w + lin3_b)
// ---------------------------------------------------------------------------
__global__ __launch_bounds__(256) void k_post(const float* __restrict__ x,
                                              const float* __restrict__ w2,
                                              const float* __restrict__ b2,
                                              const float* __restrict__ w3,
                                              const float* __restrict__ b3,
                                              float* __restrict__ out) {
    extern __shared__ float s[];
    float* s_w2 = s;                  // H*H
    float* s_w3 = s_w2 + H * H;       // H*H
    float* s_b2 = s_w3 + H * H;       // H
    float* s_b3 = s_b2 + H;           // H
    float* s_ag = s_b3 + H;           // TR*H
    float* s_h  = s_ag + TR * H;      // TR*H

    for (int i = threadIdx.x; i < H * H; i += 256) {
        s_w2[i] = w2[i];
        s_w3[i] = w3[i];
    }
    if (threadIdx.x < H) {
        s_b2[threadIdx.x] = b2[threadIdx.x];
        s_b3[threadIdx.x] = b3[threadIdx.x];
    }
    __syncthreads();

    const int tx = threadIdx.x & 31, ty = threadIdx.x >> 5;
    const float4* w24  = (const float4*)s_w2;
    const float4* w34  = (const float4*)s_w3;
    const float4* ag4  = (const float4*)g_agg;
    const float4* x4   = (const float4*)x;
    float4*       sag4 = (float4*)s_ag;
    float4*       sh4  = (float4*)s_h;
    float4*       o4   = (float4*)out;
    const float4 bias2 = *(const float4*)(s_b2 + 4 * tx);
    const float4 bias3 = *(const float4*)(s_b3 + 4 * tx);

    for (int t0 = blockIdx.x * TR; t0 < NN; t0 += gridDim.x * TR) {
        __syncwarp();
        #pragma unroll
        for (int i = 0; i < 8; i++) {
            int r = 8 * ty + i, row = t0 + r;
            float4 v = make_float4(0.f, 0.f, 0.f, 0.f);
            if (row < NN) v = ag4[(size_t)row * 32 + tx];
            sag4[r * 32 + tx] = v;
        }
        __syncwarp();

        float h[8][4];
        #pragma unroll
        for (int i = 0; i < 8; i++) {
            h[i][0] = bias2.x; h[i][1] = bias2.y;
            h[i][2] = bias2.z; h[i][3] = bias2.w;
        }
        #pragma unroll 2
        for (int k = 0; k < H; k++) {
            const float4 bf = w24[k * 32 + tx];
            #pragma unroll
            for (int i = 0; i < 8; i++) {
                const float a = s_ag[(8 * ty + i) * H + k];
                h[i][0] = fmaf(a, bf.x, h[i][0]);
                h[i][1] = fmaf(a, bf.y, h[i][1]);
                h[i][2] = fmaf(a, bf.z, h[i][2]);
                h[i][3] = fmaf(a, bf.w, h[i][3]);
            }
        }
        #pragma unroll
        for (int i = 0; i < 8; i++) {
            float4 o = make_float4(ssp(h[i][0]), ssp(h[i][1]),
                                   ssp(h[i][2]), ssp(h[i][3]));
            sh4[(8 * ty + i) * 32 + tx] = o;
        }
        __syncwarp();

        float o[8][4];
        #pragma unroll
        for (int i = 0; i < 8; i++) {
            o[i][0] = bias3.x; o[i][1] = bias3.y;
            o[i][2] = bias3.z; o[i][3] = bias3.w;
        }
        #pragma unroll 2
        for (int k = 0; k < H; k++) {
            const float4 bf = w34[k * 32 + tx];
            #pragma unroll
            for (int i = 0; i < 8; i++) {
                const float a = s_h[(8 * ty + i) * H + k];
                o[i][0] = fmaf(a, bf.x, o[i][0]);
                o[i][1] = fmaf(a, bf.y, o[i][1]);
                o[i][2] = fmaf(a, bf.z, o[i][2]);
                o[i][3] = fmaf(a, bf.w, o[i][3]);
            }
        }
        #pragma unroll
        for (int i = 0; i < 8; i++) {
            int row = t0 + 8 * ty + i;
            if (row < NN) {
                float4 xr = x4[(size_t)row * 32 + tx];
                float4 r  = make_float4(xr.x + o[i][0], xr.y + o[i][1],
                                        xr.z + o[i][2], xr.w + o[i][3]);
                o4[(size_t)row * 32 + tx] = r;
            }
        }
    }
}

// ---------------------------------------------------------------------------
extern "C" void kernel_launch(void* const* d_in, const int* in_sizes, int n_in,
                              void* d_out, int out_size) {
    const float* x      = (const float*)d_in[0];
    const float* ea     = (const float*)d_in[1];
    const float* ew     = (const float*)d_in[2];
    const float* lin1_w = (const float*)d_in[3];
    const float* lin1_b = (const float*)d_in[4];
    const float* cf1_w  = (const float*)d_in[5];
    const float* cf2_w  = (const float*)d_in[6];
    const float* cf2_b  = (const float*)d_in[7];
    const float* lin2_w = (const float*)d_in[8];
    const float* lin2_b = (const float*)d_in[9];
    const float* lin3_w = (const float*)d_in[10];
    const float* lin3_b = (const float*)d_in[11];
    const int*   ei     = (const int*)d_in[12];   // int32 [2, E]
    float* out = (float*)d_out;

    const int E = in_sizes[2];   // edge_weight has E elements

    const int smem_node = (H * H + H + TR * H) * (int)sizeof(float);
    const int smem_edge = (EC * H + H * H + H + TR * EC + TR * H) * (int)sizeof(float);
    const int smem_post = (2 * H * H + 2 * H + 2 * TR * H) * (int)sizeof(float);

    cudaFuncSetAttribute(k_node_proj, cudaFuncAttributeMaxDynamicSharedMemorySize, smem_node);
    cudaFuncSetAttribute(k_edges,     cudaFuncAttributeMaxDynamicSharedMemorySize, smem_edge);
    cudaFuncSetAttribute(k_post,      cudaFuncAttributeMaxDynamicSharedMemorySize, smem_post);

    {
        const size_t n4 = (size_t)NN * H / 4;
        const int thr = 256;
        const int blk = (int)((n4 + thr - 1) / thr);
        k_zero_agg<<<blk, thr>>>();
    }

    k_node_proj<<<296, 256, smem_node>>>(x, lin1_w, lin1_b);
    k_edges<<<148, 256, smem_edge>>>(ea, ew, cf1_w, cf2_w, cf2_b, ei, E);
    k_post<<<148, 256, smem_post>>>(x, lin2_w, lin2_b, lin3_w, lin3_b, out);
}